// round 8
// baseline (speedup 1.0000x reference)
#include <cuda_runtime.h>
#include <cstdint>

// Problem constants
#define B_    2
#define T_    2048
#define C_    1024
#define NH_   16
#define HD_   64
#define M_    (B_ * T_)     // 4096
#define NQKV_ (3 * C_)      // 3072

// Scratch (device globals: allocation-free)
__device__ float g_qkv[(size_t)M_ * NQKV_];      // qkv activations (tf32 bits, d-perm16)
__device__ float g_att[(size_t)M_ * C_];         // attention out  (tf32 bits, k-perm16)
__device__ float g_xt [(size_t)M_ * C_];         // x   -> tf32, k-perm16
__device__ float g_wqkvt[(size_t)C_ * NQKV_];    // Wqkv^T -> tf32 [N][K], k-perm16
__device__ float g_wprojt[(size_t)C_ * C_];      // Wproj^T -> tf32 [N][K], k-perm16

// ---------------------------------------------------------------------------
// helpers
// ---------------------------------------------------------------------------
__device__ __forceinline__ uint32_t f2tf32(float f) {
    uint32_t u;
    asm volatile("cvt.rna.tf32.f32 %0, %1;" : "=r"(u) : "f"(f));
    return u;
}
__device__ __forceinline__ float tf32f(float f) { return __uint_as_float(f2tf32(f)); }
__device__ __forceinline__ float ex2f(float x) {
    float y;
    asm volatile("ex2.approx.ftz.f32 %0, %1;" : "=f"(y) : "f"(x));
    return y;
}
__device__ __forceinline__ void cp16(uint32_t dsm, const void* src) {
    asm volatile("cp.async.ca.shared.global [%0], [%1], 16;" :: "r"(dsm), "l"(src));
}
#define CP_COMMIT() asm volatile("cp.async.commit_group;")
#define CP_WAIT0()  asm volatile("cp.async.wait_group 0;")

// within-16 k-permutation (4x4 transpose, involution): storage pos of true k.
// Lane t4's mma k-slots {t4, t4+4, t4+8, t4+12} sit at positions 4*t4..4*t4+3
// -> one LDS.128 per fragment row per 16-k chunk.
__device__ __forceinline__ int pos16(int k) { return ((k & 3) << 2) | (k >> 2); }

#define MMA_TF32(d, a0,a1,a2,a3, b0,b1)                                   \
    asm volatile("mma.sync.aligned.m16n8k8.row.col.f32.tf32.tf32.f32 "    \
        "{%0,%1,%2,%3}, {%4,%5,%6,%7}, {%8,%9}, {%0,%1,%2,%3};"           \
        : "+f"((d)[0]), "+f"((d)[1]), "+f"((d)[2]), "+f"((d)[3])          \
        : "r"(a0), "r"(a1), "r"(a2), "r"(a3), "r"(b0), "r"(b1))

// ---------------------------------------------------------------------------
// cvt kernels: fp32 -> tf32 with within-16 k transpose; weights also transposed.
// ---------------------------------------------------------------------------
// x rows: each thread handles one 16-float group = 4x4 register transpose.
__global__ void cvt_x_perm16(const float4* __restrict__ in,
                             float4* __restrict__ out, int n16) {
    int i = blockIdx.x * blockDim.x + threadIdx.x;
    if (i < n16) {
        float4 u0 = in[4*i], u1 = in[4*i+1], u2 = in[4*i+2], u3 = in[4*i+3];
        float4 o0, o1, o2, o3;   // out pos 4b+a holds true k=4a+b
        o0.x = tf32f(u0.x); o0.y = tf32f(u1.x); o0.z = tf32f(u2.x); o0.w = tf32f(u3.x);
        o1.x = tf32f(u0.y); o1.y = tf32f(u1.y); o1.z = tf32f(u2.y); o1.w = tf32f(u3.y);
        o2.x = tf32f(u0.z); o2.y = tf32f(u1.z); o2.z = tf32f(u2.z); o2.w = tf32f(u3.z);
        o3.x = tf32f(u0.w); o3.y = tf32f(u1.w); o3.z = tf32f(u2.w); o3.w = tf32f(u3.w);
        out[4*i] = o0; out[4*i+1] = o1; out[4*i+2] = o2; out[4*i+3] = o3;
    }
}

// W [K][N] -> W' [N][K] (k pos16-permuted within 16-groups), tiled via smem.
__global__ void cvt_transpose_perm(const float* __restrict__ in,
                                   float* __restrict__ out, int K, int N) {
    __shared__ float t[32][33];
    const int k0 = blockIdx.y * 32, n0 = blockIdx.x * 32;
    const int tx = threadIdx.x, ty = threadIdx.y;
#pragma unroll
    for (int i = 0; i < 4; i++)
        t[ty + 8*i][tx] = in[(size_t)(k0 + ty + 8*i) * N + n0 + tx];
    __syncthreads();
    const int kp = (tx & ~15) | pos16(tx & 15);
#pragma unroll
    for (int i = 0; i < 4; i++) {
        int n = ty + 8*i;
        out[(size_t)(n0 + n) * K + k0 + kp] = tf32f(t[tx][n]);
    }
}

// ---------------------------------------------------------------------------
// TF32 GEMM + bias.  C[M,N] = A[M,K] @ B'[N,K]^T + bias.
// 128 threads / 4 warps, warp tile 64x64, 128x128x32 block tile, 2-stage
// cp.async, SINGLE barrier per k-tile (wait -> barrier -> issue -> compute).
// perm16 operands: all fragment loads are LDS.128.  Stride 48 (==16 mod 32):
// quad index 4g+t4 distinct per 8-lane phase -> conflict-free.
// PERM_OUT: write columns pos16-scattered + tf32-rounded (feeds attention).
// ---------------------------------------------------------------------------
#define GST 48
#define STG (128 * GST)                    // floats per operand per stage
#define GEMM_SMEM (2 * 2 * STG * 4)        // 98304 B

template<bool PERM_OUT>
__global__ __launch_bounds__(128, 2)
void gemm_tc(const float* __restrict__ A, const float* __restrict__ Bm,
             const float* __restrict__ bias, float* __restrict__ Cm,
             int M, int N, int K) {
    extern __shared__ float smg[];

    const int tid  = threadIdx.x;
    const int lane = tid & 31, warp = tid >> 5;
    const int wm = warp >> 1, wn = warp & 1;     // 2x2 warp grid, 64x64 tiles
    const int g  = lane >> 2, t4 = lane & 3;
    const int row0 = blockIdx.y * 128, col0 = blockIdx.x * 128;

    const uint32_t sbase = (uint32_t)__cvta_generic_to_shared(smg);

    auto issue = [&](int kt) {
        const int buf = kt & 1;
        const uint32_t sA = sbase + (uint32_t)(buf * 2 * STG) * 4;
        const uint32_t sB = sA + (uint32_t)STG * 4;
#pragma unroll
        for (int i = 0; i < 8; i++) {
            int idx = tid + 128 * i;
            int r = idx >> 3, kc = (idx & 7) << 2;
            cp16(sA + (uint32_t)(r * GST + kc) * 4,
                 &A[(size_t)(row0 + r) * K + kt * 32 + kc]);
        }
#pragma unroll
        for (int i = 0; i < 8; i++) {
            int idx = tid + 128 * i;
            int r = idx >> 3, kc = (idx & 7) << 2;
            cp16(sB + (uint32_t)(r * GST + kc) * 4,
                 &Bm[(size_t)(col0 + r) * K + kt * 32 + kc]);
        }
    };

    float acc[4][8][4];
#pragma unroll
    for (int mt = 0; mt < 4; mt++)
#pragma unroll
        for (int nt = 0; nt < 8; nt++)
#pragma unroll
            for (int c = 0; c < 4; c++) acc[mt][nt][c] = 0.f;

    const int KT = K >> 5;
    issue(0); CP_COMMIT();

    for (int kt = 0; kt < KT; kt++) {
        CP_WAIT0();          // tile kt landed (issued one iteration ago)
        __syncthreads();     // visible to all; all warps done with other buffer
        if (kt + 1 < KT) { issue(kt + 1); CP_COMMIT(); }

        const float* Ab = smg + (kt & 1) * 2 * STG;
        const float* Bb = Ab + STG;

#pragma unroll
        for (int kk = 0; kk < 32; kk += 16) {
            uint4 ra[4][2];
#pragma unroll
            for (int mt = 0; mt < 4; mt++) {
                const float* ap = Ab + (wm*64 + mt*16 + g) * GST + kk + 4*t4;
                ra[mt][0] = *reinterpret_cast<const uint4*>(ap);            // row g
                ra[mt][1] = *reinterpret_cast<const uint4*>(ap + 8*GST);    // row g+8
            }
#pragma unroll
            for (int nt = 0; nt < 8; nt++) {
                uint4 rbv = *reinterpret_cast<const uint4*>(
                    Bb + (wn*64 + nt*8 + g) * GST + kk + 4*t4);
#pragma unroll
                for (int mt = 0; mt < 4; mt++)
                    MMA_TF32(acc[mt][nt], ra[mt][0].x, ra[mt][1].x,
                             ra[mt][0].y, ra[mt][1].y, rbv.x, rbv.y);
#pragma unroll
                for (int mt = 0; mt < 4; mt++)
                    MMA_TF32(acc[mt][nt], ra[mt][0].z, ra[mt][1].z,
                             ra[mt][0].w, ra[mt][1].w, rbv.z, rbv.w);
            }
        }
    }

    // epilogue: + bias (true columns); PERM_OUT scatters by pos16
#pragma unroll
    for (int mt = 0; mt < 4; mt++) {
        const int rA = row0 + wm*64 + mt*16 + g;
        const int rB = rA + 8;
#pragma unroll
        for (int nt = 0; nt < 8; nt++) {
            const int c = col0 + wn*64 + nt*8 + 2*t4;
            const float b0 = bias[c], b1 = bias[c + 1];
            float v0 = acc[mt][nt][0] + b0, v1 = acc[mt][nt][1] + b1;
            float v2 = acc[mt][nt][2] + b0, v3 = acc[mt][nt][3] + b1;
            if (PERM_OUT) {
                const int cb = col0 + wn*64 + ((nt >> 1) << 4);
                const int w  = ((nt & 1) << 3) | (2*t4);
                const int pp = ((w & 3) << 2) | (w >> 2);   // pos16(w); w+1 -> pp+4
                Cm[(size_t)rA * N + cb + pp]     = tf32f(v0);
                Cm[(size_t)rA * N + cb + pp + 4] = tf32f(v1);
                Cm[(size_t)rB * N + cb + pp]     = tf32f(v2);
                Cm[(size_t)rB * N + cb + pp + 4] = tf32f(v3);
            } else {
                *reinterpret_cast<float2*>(&Cm[(size_t)rA * N + c]) = make_float2(v0, v1);
                *reinterpret_cast<float2*>(&Cm[(size_t)rB * N + c]) = make_float2(v2, v3);
            }
        }
    }
}

// ---------------------------------------------------------------------------
// Tensor-core flash attention, cp.async double-buffered K/V.
// qkv arrives d-perm16'd -> Q/K/P fragments are LDS.128 (strides 80 == 16
// mod 32: conflict-free).  V position-indexed -> O accumulates in position
// space == perm16 space; epilogue is a direct float2 write that the proj
// GEMM consumes natively.
// ---------------------------------------------------------------------------
#define QS_ST 80
#define KS_ST 80
#define VS_ST 72
#define PS_ST 80
#define KV_TILE (64 * KS_ST + 64 * VS_ST)
#define ATTN_SMEM ((128*QS_ST + 2*KV_TILE + 128*PS_ST) * 4)   // 159744 B

#define MASKVAL (-6e30f)
#define MINIT   (-1e30f)

__global__ __launch_bounds__(256, 1)
void attn_tc(const float* __restrict__ qkv, float* __restrict__ att) {
    extern __shared__ float sm[];
    float* Qs  = sm;                        // [128][QS_ST]
    float* KV0 = Qs + 128*QS_ST;            // 2 stages of K[64]+V[64]
    float* Ps  = KV0 + 2*KV_TILE;           // [128][PS_ST]

    const int tid  = threadIdx.x;
    const int lane = tid & 31, warp = tid >> 5;
    const int g = lane >> 2, t4 = lane & 3;
    const int qb = gridDim.x - 1 - blockIdx.x;   // heavy tiles first
    const int bh = blockIdx.y;
    const int b = bh >> 4, h = bh & 15;
    const int m0 = qb * 128;
    const int rb = warp * 16;

    const float* qbase = qkv + ((size_t)b*T_ + m0)*NQKV_ + h*HD_;
    const float* kbase = qkv + (size_t)b*T_*NQKV_ + h*HD_ + C_;
    const float* vbase = kbase + C_;

    const uint32_t skv = (uint32_t)__cvta_generic_to_shared(KV0);

    auto issue = [&](int kvb) {
        const uint32_t sK = skv + (uint32_t)((kvb & 1) * KV_TILE) * 4;
        const uint32_t sV = sK + (uint32_t)(64 * KS_ST) * 4;
        const int jb = kvb * 64;
#pragma unroll
        for (int i = 0; i < 4; i++) {
            int idx = tid + 256 * i;
            int j = idx >> 4, d4 = (idx & 15) << 2;
            cp16(sK + (uint32_t)(j*KS_ST + d4) * 4, &kbase[(size_t)(jb+j)*NQKV_ + d4]);
        }
#pragma unroll
        for (int i = 0; i < 4; i++) {
            int idx = tid + 256 * i;
            int j = idx >> 4, d4 = (idx & 15) << 2;
            cp16(sV + (uint32_t)(j*VS_ST + d4) * 4, &vbase[(size_t)(jb+j)*NQKV_ + d4]);
        }
    };

    issue(0); CP_COMMIT();

    // Q tile: scale by (1/8)*log2(e), re-round, copy-through (already perm16)
    const float qscale = 0.125f * 1.44269504088896340736f;
    for (int idx = tid; idx < 128*16; idx += 256) {
        int r = idx >> 4, d4 = (idx & 15) << 2;
        float4 v = *reinterpret_cast<const float4*>(&qbase[(size_t)r*NQKV_ + d4]);
        float* q = &Qs[r*QS_ST + d4];
        q[0] = tf32f(v.x * qscale);
        q[1] = tf32f(v.y * qscale);
        q[2] = tf32f(v.z * qscale);
        q[3] = tf32f(v.w * qscale);
    }

    float o[8][4];
    float mrow[2] = {MINIT, MINIT}, lrow[2] = {0.f, 0.f};
#pragma unroll
    for (int nt = 0; nt < 8; nt++)
#pragma unroll
        for (int c = 0; c < 4; c++) o[nt][c] = 0.f;

    const int nkv = 2*qb + 2;
    for (int kvb = 0; kvb < nkv; kvb++) {
        const int jb = kvb * 64;
        CP_WAIT0();
        __syncthreads();
        if (kvb + 1 < nkv) { issue(kvb + 1); CP_COMMIT(); }

        const float* Ks = KV0 + (kvb & 1) * KV_TILE;
        const float* Vs = Ks + 64 * KS_ST;

        if (jb > m0 + rb + 15) continue;

        // ---- S = Q' @ K^T (both d-perm16: dot product invariant) ----
        float s[8][4];
#pragma unroll
        for (int nt = 0; nt < 8; nt++)
#pragma unroll
            for (int c = 0; c < 4; c++) s[nt][c] = 0.f;

#pragma unroll
        for (int kk = 0; kk < 64; kk += 16) {
            const float* ap = &Qs[(rb + g)*QS_ST + kk + 4*t4];
            uint4 qa0 = *reinterpret_cast<const uint4*>(ap);
            uint4 qa1 = *reinterpret_cast<const uint4*>(ap + 8*QS_ST);
#pragma unroll
            for (int nt = 0; nt < 8; nt++) {
                uint4 kf = *reinterpret_cast<const uint4*>(
                    &Ks[(nt*8 + g)*KS_ST + kk + 4*t4]);
                MMA_TF32(s[nt], qa0.x, qa1.x, qa0.y, qa1.y, kf.x, kf.y);
                MMA_TF32(s[nt], qa0.z, qa1.z, qa0.w, qa1.w, kf.z, kf.w);
            }
        }

        // ---- causal mask (true j coordinates; K rows are natural) ----
        if (jb + 63 > m0 + rb) {
            const int r0 = m0 + rb + g, r1 = r0 + 8;
#pragma unroll
            for (int nt = 0; nt < 8; nt++) {
                int cb = jb + nt*8 + 2*t4;
                if (cb     > r0) s[nt][0] = MASKVAL;
                if (cb + 1 > r0) s[nt][1] = MASKVAL;
                if (cb     > r1) s[nt][2] = MASKVAL;
                if (cb + 1 > r1) s[nt][3] = MASKVAL;
            }
        }

        // ---- online softmax (exp2 domain) ----
        float mx0 = MINIT, mx1 = MINIT;
#pragma unroll
        for (int nt = 0; nt < 8; nt++) {
            mx0 = fmaxf(mx0, fmaxf(s[nt][0], s[nt][1]));
            mx1 = fmaxf(mx1, fmaxf(s[nt][2], s[nt][3]));
        }
        mx0 = fmaxf(mx0, __shfl_xor_sync(0xffffffffu, mx0, 1));
        mx0 = fmaxf(mx0, __shfl_xor_sync(0xffffffffu, mx0, 2));
        mx1 = fmaxf(mx1, __shfl_xor_sync(0xffffffffu, mx1, 1));
        mx1 = fmaxf(mx1, __shfl_xor_sync(0xffffffffu, mx1, 2));
        const float mn0 = fmaxf(mrow[0], mx0), mn1 = fmaxf(mrow[1], mx1);
        const float al0 = ex2f(mrow[0] - mn0), al1 = ex2f(mrow[1] - mn1);
        mrow[0] = mn0; mrow[1] = mn1;

        float ls0 = 0.f, ls1 = 0.f;
#pragma unroll
        for (int nt = 0; nt < 8; nt++) {
            s[nt][0] = ex2f(s[nt][0] - mn0);
            s[nt][1] = ex2f(s[nt][1] - mn0);
            s[nt][2] = ex2f(s[nt][2] - mn1);
            s[nt][3] = ex2f(s[nt][3] - mn1);
            ls0 += s[nt][0] + s[nt][1];
            ls1 += s[nt][2] + s[nt][3];
            o[nt][0] *= al0; o[nt][1] *= al0;
            o[nt][2] *= al1; o[nt][3] *= al1;
            // stage P j-pos16-scattered (tf32) for LDS.128 PV fragments
            const int base = (nt >> 1) << 4;
            const int w  = ((nt & 1) << 3) | (2*t4);
            const int pp = ((w & 3) << 2) | (w >> 2);
            float* p0 = &Ps[(rb + g)*PS_ST + base];
            float* p1 = &Ps[(rb + g + 8)*PS_ST + base];
            p0[pp]     = tf32f(s[nt][0]);
            p0[pp + 4] = tf32f(s[nt][1]);
            p1[pp]     = tf32f(s[nt][2]);
            p1[pp + 4] = tf32f(s[nt][3]);
        }
        ls0 += __shfl_xor_sync(0xffffffffu, ls0, 1);
        ls0 += __shfl_xor_sync(0xffffffffu, ls0, 2);
        ls1 += __shfl_xor_sync(0xffffffffu, ls1, 1);
        ls1 += __shfl_xor_sync(0xffffffffu, ls1, 2);
        lrow[0] = lrow[0]*al0 + ls0;
        lrow[1] = lrow[1]*al1 + ls1;

        __syncwarp();

        // ---- O += P @ V  (A j-perm16 storage <-> V natural rows) ----
#pragma unroll
        for (int kk = 0; kk < 64; kk += 16) {
            const float* ap = &Ps[(rb + g)*PS_ST + kk + 4*t4];
            uint4 pa0 = *reinterpret_cast<const uint4*>(ap);
            uint4 pa1 = *reinterpret_cast<const uint4*>(ap + 8*PS_ST);
#pragma unroll
            for (int nt = 0; nt < 8; nt++) {
                const float* bp = &Vs[(kk + t4)*VS_ST + nt*8 + g];
                MMA_TF32(o[nt], pa0.x, pa1.x, pa0.y, pa1.y,
                         __float_as_uint(bp[0]), __float_as_uint(bp[4*VS_ST]));
                MMA_TF32(o[nt], pa0.z, pa1.z, pa0.w, pa1.w,
                         __float_as_uint(bp[8*VS_ST]), __float_as_uint(bp[12*VS_ST]));
            }
        }
    }

    // ---- epilogue: normalize; position-space write == perm16'd att ----
    const float inv0 = 1.0f / lrow[0], inv1 = 1.0f / lrow[1];
    const size_t r0 = (size_t)b*T_ + m0 + rb + g;
    const size_t r1 = r0 + 8;
#pragma unroll
    for (int nt = 0; nt < 8; nt++) {
        const int c = h*HD_ + nt*8 + 2*t4;
        *reinterpret_cast<float2*>(&att[r0*C_ + c]) =
            make_float2(tf32f(o[nt][0] * inv0), tf32f(o[nt][1] * inv0));
        *reinterpret_cast<float2*>(&att[r1*C_ + c]) =
            make_float2(tf32f(o[nt][2] * inv1), tf32f(o[nt][3] * inv1));
    }
}

// ---------------------------------------------------------------------------
// Launch
// ---------------------------------------------------------------------------
extern "C" void kernel_launch(void* const* d_in, const int* in_sizes, int n_in,
                              void* d_out, int out_size) {
    const float* x     = (const float*)d_in[0];
    const float* Wqkv  = (const float*)d_in[1];
    const float* bqkv  = (const float*)d_in[2];
    const float* Wproj = (const float*)d_in[3];
    const float* bproj = (const float*)d_in[4];
    float* out = (float*)d_out;

    float *qkv_p, *att_p, *xt_p, *wq_p, *wp_p;
    cudaGetSymbolAddress((void**)&qkv_p, g_qkv);
    cudaGetSymbolAddress((void**)&att_p, g_att);
    cudaGetSymbolAddress((void**)&xt_p,  g_xt);
    cudaGetSymbolAddress((void**)&wq_p,  g_wqkvt);
    cudaGetSymbolAddress((void**)&wp_p,  g_wprojt);

    cudaFuncSetAttribute(gemm_tc<true>,
                         cudaFuncAttributeMaxDynamicSharedMemorySize, GEMM_SMEM);
    cudaFuncSetAttribute(gemm_tc<false>,
                         cudaFuncAttributeMaxDynamicSharedMemorySize, GEMM_SMEM);
    cudaFuncSetAttribute(attn_tc,
                         cudaFuncAttributeMaxDynamicSharedMemorySize, ATTN_SMEM);

    // 0) operand prep: x k-perm16; weights transposed [N][K] + k-perm16
    cvt_x_perm16<<<(M_*C_/16)/256, 256>>>((const float4*)x, (float4*)xt_p, M_*C_/16);
    {
        dim3 blk(32, 8);
        dim3 gq(NQKV_/32, C_/32);
        cvt_transpose_perm<<<gq, blk>>>(Wqkv, wq_p, C_, NQKV_);
        dim3 gp(C_/32, C_/32);
        cvt_transpose_perm<<<gp, blk>>>(Wproj, wp_p, C_, C_);
    }

    // 1) QKV GEMM -> d-perm16'd tf32 qkv
    dim3 g1(NQKV_/128, M_/128);
    gemm_tc<true><<<g1, 128, GEMM_SMEM>>>(xt_p, wq_p, bqkv, qkv_p, M_, NQKV_, C_);

    // 2) Flash attention -> k-perm16'd tf32 att
    dim3 g2(T_/128, B_*NH_);
    attn_tc<<<g2, 256, ATTN_SMEM>>>(qkv_p, att_p);

    // 3) Output projection -> natural fp32 out
    dim3 g3(C_/128, M_/128);
    gemm_tc<false><<<g3, 128, GEMM_SMEM>>>(att_p, wp_p, bproj, out, M_, C_, C_);
}

// round 9
// speedup vs baseline: 1.1344x; 1.1344x over previous
#include <cuda_runtime.h>
#include <cstdint>

// Problem constants
#define B_    2
#define T_    2048
#define C_    1024
#define NH_   16
#define HD_   64
#define M_    (B_ * T_)     // 4096
#define NQKV_ (3 * C_)      // 3072

// Scratch (device globals: allocation-free)
__device__ float g_qkv[(size_t)M_ * NQKV_];      // qkv activations (tf32 bits, d-permuted)
__device__ float g_att[(size_t)M_ * C_];         // attention out  (tf32 bits, k-permuted)
__device__ float g_xt [(size_t)M_ * C_];         // x   -> tf32, k-permuted
__device__ float g_wqkvt[(size_t)C_ * NQKV_];    // Wqkv^T -> tf32 [N][K], k-permuted
__device__ float g_wprojt[(size_t)C_ * C_];      // Wproj^T -> tf32 [N][K], k-permuted

// ---------------------------------------------------------------------------
// helpers
// ---------------------------------------------------------------------------
__device__ __forceinline__ uint32_t f2tf32(float f) {
    uint32_t u;
    asm volatile("cvt.rna.tf32.f32 %0, %1;" : "=r"(u) : "f"(f));
    return u;
}
__device__ __forceinline__ float tf32f(float f) { return __uint_as_float(f2tf32(f)); }
__device__ __forceinline__ float ex2f(float x) {
    float y;
    asm volatile("ex2.approx.ftz.f32 %0, %1;" : "=f"(y) : "f"(x));
    return y;
}
__device__ __forceinline__ void cp16(uint32_t dsm, const void* src) {
    asm volatile("cp.async.ca.shared.global [%0], [%1], 16;" :: "r"(dsm), "l"(src));
}
#define CP_COMMIT() asm volatile("cp.async.commit_group;")
#define CP_WAIT0()  asm volatile("cp.async.wait_group 0;")

// within-8 k-permutation: storage position of true k.  p(k)=((k&3)<<1)|(k>>2)
// -> mma slots (t4, t4+4) sit at adjacent storage positions (2*t4, 2*t4+1).
__device__ __host__ __forceinline__ int perm8(int k) { return ((k & 3) << 1) | (k >> 2); }

#define MMA_TF32(d, a0,a1,a2,a3, b0,b1)                                   \
    asm volatile("mma.sync.aligned.m16n8k8.row.col.f32.tf32.tf32.f32 "    \
        "{%0,%1,%2,%3}, {%4,%5,%6,%7}, {%8,%9}, {%0,%1,%2,%3};"           \
        : "+f"((d)[0]), "+f"((d)[1]), "+f"((d)[2]), "+f"((d)[3])          \
        : "r"(a0), "r"(a1), "r"(a2), "r"(a3), "r"(b0), "r"(b1))

// ---------------------------------------------------------------------------
// cvt kernels: fp32 -> tf32 with within-8 k-permute; weights also transposed.
// ---------------------------------------------------------------------------
__global__ void cvt_x_perm(const float4* __restrict__ in,
                           float4* __restrict__ out, int n8) {
    int i = blockIdx.x * blockDim.x + threadIdx.x;
    if (i < n8) {
        float4 u = in[2*i], v = in[2*i + 1];
        float4 o0, o1;   // positions 0..3 <- k {0,4,1,5}; 4..7 <- k {2,6,3,7}
        o0.x = tf32f(u.x); o0.y = tf32f(v.x); o0.z = tf32f(u.y); o0.w = tf32f(v.y);
        o1.x = tf32f(u.z); o1.y = tf32f(v.z); o1.z = tf32f(u.w); o1.w = tf32f(v.w);
        out[2*i] = o0; out[2*i + 1] = o1;
    }
}

// W [K][N] -> W' [N][K] (k-permuted within 8-groups), tiled via smem.
__global__ void cvt_transpose_perm(const float* __restrict__ in,
                                   float* __restrict__ out, int K, int N) {
    __shared__ float t[32][33];
    const int k0 = blockIdx.y * 32, n0 = blockIdx.x * 32;
    const int tx = threadIdx.x, ty = threadIdx.y;
#pragma unroll
    for (int i = 0; i < 4; i++)
        t[ty + 8*i][tx] = in[(size_t)(k0 + ty + 8*i) * N + n0 + tx];
    __syncthreads();
    const int kp = (tx & ~7) | perm8(tx & 7);
#pragma unroll
    for (int i = 0; i < 4; i++) {
        int n = ty + 8*i;
        out[(size_t)(n0 + n) * K + k0 + kp] = tf32f(t[tx][n]);
    }
}

// ---------------------------------------------------------------------------
// TF32 GEMM + bias.  C[M,N] = A[M,K] @ B'[N,K]^T + bias.
// 128 threads / 4 warps, warp tile 64x64 (2x2 warp grid), 128x128x32 block
// tile, 2-stage cp.async, SINGLE barrier per k-tile:
//   wait0 -> barrier -> issue(kt+1) -> compute(kt)
// (the top barrier proves all warps finished compute(kt-1) on the other
// buffer, so issuing into it after the barrier is race-free).
// Smem [row][32k] stride 40 (==8 mod 32): LDS.64 fragment loads conflict-free.
// PERM_OUT: write columns k-permuted + tf32-rounded (feeds attention).
// ---------------------------------------------------------------------------
#define GST 40
#define STG (128 * GST)                    // floats per operand per stage
#define GEMM_SMEM (2 * 2 * STG * 4)        // 81920 B

template<bool PERM_OUT>
__global__ __launch_bounds__(128, 2)
void gemm_tc(const float* __restrict__ A, const float* __restrict__ Bm,
             const float* __restrict__ bias, float* __restrict__ Cm,
             int M, int N, int K) {
    extern __shared__ float smg[];

    const int tid  = threadIdx.x;
    const int lane = tid & 31, warp = tid >> 5;
    const int wm = warp >> 1, wn = warp & 1;     // 2x2 warp grid, 64x64 tiles
    const int g  = lane >> 2, t4 = lane & 3;
    const int row0 = blockIdx.y * 128, col0 = blockIdx.x * 128;

    const uint32_t sbase = (uint32_t)__cvta_generic_to_shared(smg);

    auto issue = [&](int kt) {
        const int buf = kt & 1;
        const uint32_t sA = sbase + (uint32_t)(buf * 2 * STG) * 4;
        const uint32_t sB = sA + (uint32_t)STG * 4;
#pragma unroll
        for (int i = 0; i < 8; i++) {
            int idx = tid + 128 * i;
            int r = idx >> 3, kc = (idx & 7) << 2;
            cp16(sA + (uint32_t)(r * GST + kc) * 4,
                 &A[(size_t)(row0 + r) * K + kt * 32 + kc]);
        }
#pragma unroll
        for (int i = 0; i < 8; i++) {
            int idx = tid + 128 * i;
            int r = idx >> 3, kc = (idx & 7) << 2;
            cp16(sB + (uint32_t)(r * GST + kc) * 4,
                 &Bm[(size_t)(col0 + r) * K + kt * 32 + kc]);
        }
    };

    float acc[4][8][4];
#pragma unroll
    for (int mt = 0; mt < 4; mt++)
#pragma unroll
        for (int nt = 0; nt < 8; nt++)
#pragma unroll
            for (int c = 0; c < 4; c++) acc[mt][nt][c] = 0.f;

    const int KT = K >> 5;
    issue(0); CP_COMMIT();

    for (int kt = 0; kt < KT; kt++) {
        CP_WAIT0();          // tile kt landed (issued last iteration)
        __syncthreads();     // all warps past compute(kt-1) on the other buffer
        if (kt + 1 < KT) { issue(kt + 1); CP_COMMIT(); }

        const float* Ab = smg + (kt & 1) * 2 * STG;
        const float* Bb = Ab + STG;

#pragma unroll
        for (int kk = 0; kk < 32; kk += 8) {
            uint32_t ra[4][4], rb[8][2];
#pragma unroll
            for (int mt = 0; mt < 4; mt++) {
                const float* ap = Ab + (wm*64 + mt*16 + g) * GST + kk + 2*t4;
                float2 p0 = *reinterpret_cast<const float2*>(ap);
                float2 p1 = *reinterpret_cast<const float2*>(ap + 8*GST);
                ra[mt][0] = __float_as_uint(p0.x);   // (g,   t4)
                ra[mt][2] = __float_as_uint(p0.y);   // (g,   t4+4)
                ra[mt][1] = __float_as_uint(p1.x);   // (g+8, t4)
                ra[mt][3] = __float_as_uint(p1.y);   // (g+8, t4+4)
            }
#pragma unroll
            for (int nt = 0; nt < 8; nt++) {
                const float* bp = Bb + (wn*64 + nt*8 + g) * GST + kk + 2*t4;
                float2 pb = *reinterpret_cast<const float2*>(bp);
                rb[nt][0] = __float_as_uint(pb.x);   // (t4,   n g)
                rb[nt][1] = __float_as_uint(pb.y);   // (t4+4, n g)
            }
#pragma unroll
            for (int mt = 0; mt < 4; mt++)
#pragma unroll
                for (int nt = 0; nt < 8; nt++)
                    MMA_TF32(acc[mt][nt], ra[mt][0], ra[mt][1], ra[mt][2],
                             ra[mt][3], rb[nt][0], rb[nt][1]);
        }
    }

    // epilogue: + bias (true columns); PERM_OUT scatters within 8-groups
    const int pos0 = perm8(2 * t4);   // position of col 2t4; col 2t4+1 at pos0+2
#pragma unroll
    for (int mt = 0; mt < 4; mt++) {
        const int rA = row0 + wm*64 + mt*16 + g;
        const int rB = rA + 8;
#pragma unroll
        for (int nt = 0; nt < 8; nt++) {
            const int cb = col0 + wn*64 + nt*8;
            const int c  = cb + 2*t4;
            const float b0 = bias[c], b1 = bias[c + 1];
            float v0 = acc[mt][nt][0] + b0, v1 = acc[mt][nt][1] + b1;
            float v2 = acc[mt][nt][2] + b0, v3 = acc[mt][nt][3] + b1;
            if (PERM_OUT) {
                Cm[(size_t)rA * N + cb + pos0]     = tf32f(v0);
                Cm[(size_t)rA * N + cb + pos0 + 2] = tf32f(v1);
                Cm[(size_t)rB * N + cb + pos0]     = tf32f(v2);
                Cm[(size_t)rB * N + cb + pos0 + 2] = tf32f(v3);
            } else {
                *reinterpret_cast<float2*>(&Cm[(size_t)rA * N + c]) = make_float2(v0, v1);
                *reinterpret_cast<float2*>(&Cm[(size_t)rB * N + c]) = make_float2(v2, v3);
            }
        }
    }
}

// ---------------------------------------------------------------------------
// Tensor-core flash attention, cp.async double-buffered K/V.
// qkv arrives d-permuted (within 8-groups) -> Q/K fragments are LDS.64.
// P staged j-permuted -> PV A-fragments LDS.64.  Output written in permuted
// position space == k-permuted att, exactly what the proj GEMM consumes.
// ---------------------------------------------------------------------------
#define QS_ST 72
#define KS_ST 72
#define VS_ST 72
#define PS_ST 72
#define KV_TILE (64 * KS_ST + 64 * VS_ST)
#define ATTN_SMEM ((128*QS_ST + 2*KV_TILE + 128*PS_ST) * 4)   // 147456 B

#define MASKVAL (-6e30f)
#define MINIT   (-1e30f)

__global__ __launch_bounds__(256, 1)
void attn_tc(const float* __restrict__ qkv, float* __restrict__ att) {
    extern __shared__ float sm[];
    float* Qs  = sm;                        // [128][QS_ST]
    float* KV0 = Qs + 128*QS_ST;            // 2 stages of K[64]+V[64]
    float* Ps  = KV0 + 2*KV_TILE;           // [128][PS_ST]

    const int tid  = threadIdx.x;
    const int lane = tid & 31, warp = tid >> 5;
    const int g = lane >> 2, t4 = lane & 3;
    const int qb = gridDim.x - 1 - blockIdx.x;   // heavy tiles first
    const int bh = blockIdx.y;
    const int b = bh >> 4, h = bh & 15;
    const int m0 = qb * 128;
    const int rb = warp * 16;
    const int pos0 = perm8(2 * t4);

    const float* qbase = qkv + ((size_t)b*T_ + m0)*NQKV_ + h*HD_;
    const float* kbase = qkv + (size_t)b*T_*NQKV_ + h*HD_ + C_;
    const float* vbase = kbase + C_;

    const uint32_t skv = (uint32_t)__cvta_generic_to_shared(KV0);

    auto issue = [&](int kvb) {
        const uint32_t sK = skv + (uint32_t)((kvb & 1) * KV_TILE) * 4;
        const uint32_t sV = sK + (uint32_t)(64 * KS_ST) * 4;
        const int jb = kvb * 64;
#pragma unroll
        for (int i = 0; i < 4; i++) {
            int idx = tid + 256 * i;
            int j = idx >> 4, d4 = (idx & 15) << 2;
            cp16(sK + (uint32_t)(j*KS_ST + d4) * 4, &kbase[(size_t)(jb+j)*NQKV_ + d4]);
        }
#pragma unroll
        for (int i = 0; i < 4; i++) {
            int idx = tid + 256 * i;
            int j = idx >> 4, d4 = (idx & 15) << 2;
            cp16(sV + (uint32_t)(j*VS_ST + d4) * 4, &vbase[(size_t)(jb+j)*NQKV_ + d4]);
        }
    };

    issue(0); CP_COMMIT();

    // Q tile: scale by (1/8)*log2(e), re-round, copy-through (already permuted)
    const float qscale = 0.125f * 1.44269504088896340736f;
    for (int idx = tid; idx < 128*16; idx += 256) {
        int r = idx >> 4, d4 = (idx & 15) << 2;
        float4 v = *reinterpret_cast<const float4*>(&qbase[(size_t)r*NQKV_ + d4]);
        float* q = &Qs[r*QS_ST + d4];
        q[0] = tf32f(v.x * qscale);
        q[1] = tf32f(v.y * qscale);
        q[2] = tf32f(v.z * qscale);
        q[3] = tf32f(v.w * qscale);
    }

    float o[8][4];
    float mrow[2] = {MINIT, MINIT}, lrow[2] = {0.f, 0.f};
#pragma unroll
    for (int nt = 0; nt < 8; nt++)
#pragma unroll
        for (int c = 0; c < 4; c++) o[nt][c] = 0.f;

    const int nkv = 2*qb + 2;
    for (int kvb = 0; kvb < nkv; kvb++) {
        const int jb = kvb * 64;
        CP_WAIT0();
        __syncthreads();
        if (kvb + 1 < nkv) { issue(kvb + 1); CP_COMMIT(); }

        const float* Ks = KV0 + (kvb & 1) * KV_TILE;
        const float* Vs = Ks + 64 * KS_ST;

        if (jb > m0 + rb + 15) continue;

        // ---- S = Q' @ K^T (both d-permuted: dot product invariant) ----
        float s[8][4];
#pragma unroll
        for (int nt = 0; nt < 8; nt++)
#pragma unroll
            for (int c = 0; c < 4; c++) s[nt][c] = 0.f;

#pragma unroll
        for (int kk = 0; kk < 64; kk += 8) {
            const float* ap = &Qs[(rb + g)*QS_ST + kk + 2*t4];
            float2 qa0 = *reinterpret_cast<const float2*>(ap);
            float2 qa1 = *reinterpret_cast<const float2*>(ap + 8*QS_ST);
            uint32_t a0 = __float_as_uint(qa0.x), a2 = __float_as_uint(qa0.y);
            uint32_t a1 = __float_as_uint(qa1.x), a3 = __float_as_uint(qa1.y);
#pragma unroll
            for (int nt = 0; nt < 8; nt++) {
                float2 kf = *reinterpret_cast<const float2*>(
                    &Ks[(nt*8 + g)*KS_ST + kk + 2*t4]);
                MMA_TF32(s[nt], a0, a1, a2, a3,
                         __float_as_uint(kf.x), __float_as_uint(kf.y));
            }
        }

        // ---- causal mask (true j coordinates; K rows are natural) ----
        if (jb + 63 > m0 + rb) {
            const int r0 = m0 + rb + g, r1 = r0 + 8;
#pragma unroll
            for (int nt = 0; nt < 8; nt++) {
                int cb = jb + nt*8 + 2*t4;
                if (cb     > r0) s[nt][0] = MASKVAL;
                if (cb + 1 > r0) s[nt][1] = MASKVAL;
                if (cb     > r1) s[nt][2] = MASKVAL;
                if (cb + 1 > r1) s[nt][3] = MASKVAL;
            }
        }

        // ---- online softmax (exp2 domain) ----
        float mx0 = MINIT, mx1 = MINIT;
#pragma unroll
        for (int nt = 0; nt < 8; nt++) {
            mx0 = fmaxf(mx0, fmaxf(s[nt][0], s[nt][1]));
            mx1 = fmaxf(mx1, fmaxf(s[nt][2], s[nt][3]));
        }
        mx0 = fmaxf(mx0, __shfl_xor_sync(0xffffffffu, mx0, 1));
        mx0 = fmaxf(mx0, __shfl_xor_sync(0xffffffffu, mx0, 2));
        mx1 = fmaxf(mx1, __shfl_xor_sync(0xffffffffu, mx1, 1));
        mx1 = fmaxf(mx1, __shfl_xor_sync(0xffffffffu, mx1, 2));
        const float mn0 = fmaxf(mrow[0], mx0), mn1 = fmaxf(mrow[1], mx1);
        const float al0 = ex2f(mrow[0] - mn0), al1 = ex2f(mrow[1] - mn1);
        mrow[0] = mn0; mrow[1] = mn1;

        float ls0 = 0.f, ls1 = 0.f;
#pragma unroll
        for (int nt = 0; nt < 8; nt++) {
            s[nt][0] = ex2f(s[nt][0] - mn0);
            s[nt][1] = ex2f(s[nt][1] - mn0);
            s[nt][2] = ex2f(s[nt][2] - mn1);
            s[nt][3] = ex2f(s[nt][3] - mn1);
            ls0 += s[nt][0] + s[nt][1];
            ls1 += s[nt][2] + s[nt][3];
            o[nt][0] *= al0; o[nt][1] *= al0;
            o[nt][2] *= al1; o[nt][3] *= al1;
            // stage P j-permuted (tf32) for LDS.64 PV fragments
            float* p0 = &Ps[(rb + g)*PS_ST + nt*8];
            float* p1 = &Ps[(rb + g + 8)*PS_ST + nt*8];
            p0[pos0]     = tf32f(s[nt][0]);
            p0[pos0 + 2] = tf32f(s[nt][1]);
            p1[pos0]     = tf32f(s[nt][2]);
            p1[pos0 + 2] = tf32f(s[nt][3]);
        }
        ls0 += __shfl_xor_sync(0xffffffffu, ls0, 1);
        ls0 += __shfl_xor_sync(0xffffffffu, ls0, 2);
        ls1 += __shfl_xor_sync(0xffffffffu, ls1, 1);
        ls1 += __shfl_xor_sync(0xffffffffu, ls1, 2);
        lrow[0] = lrow[0]*al0 + ls0;
        lrow[1] = lrow[1]*al1 + ls1;

        __syncwarp();

        // ---- O += P @ V  (A j-permuted storage <-> V natural rows) ----
#pragma unroll
        for (int kk = 0; kk < 64; kk += 8) {
            const float* ap = &Ps[(rb + g)*PS_ST + kk + 2*t4];
            float2 pa0 = *reinterpret_cast<const float2*>(ap);
            float2 pa1 = *reinterpret_cast<const float2*>(ap + 8*PS_ST);
            uint32_t a0 = __float_as_uint(pa0.x), a2 = __float_as_uint(pa0.y);
            uint32_t a1 = __float_as_uint(pa1.x), a3 = __float_as_uint(pa1.y);
#pragma unroll
            for (int nt = 0; nt < 8; nt++) {
                const float* bp = &Vs[(kk + t4)*VS_ST + nt*8 + g];
                MMA_TF32(o[nt], a0, a1, a2, a3,
                         __float_as_uint(bp[0]), __float_as_uint(bp[4*VS_ST]));
            }
        }
    }

    // ---- epilogue: normalize; position-space write == permuted att ----
    const float inv0 = 1.0f / lrow[0], inv1 = 1.0f / lrow[1];
    const size_t r0 = (size_t)b*T_ + m0 + rb + g;
    const size_t r1 = r0 + 8;
#pragma unroll
    for (int nt = 0; nt < 8; nt++) {
        const int c = h*HD_ + nt*8 + 2*t4;
        *reinterpret_cast<float2*>(&att[r0*C_ + c]) =
            make_float2(tf32f(o[nt][0] * inv0), tf32f(o[nt][1] * inv0));
        *reinterpret_cast<float2*>(&att[r1*C_ + c]) =
            make_float2(tf32f(o[nt][2] * inv1), tf32f(o[nt][3] * inv1));
    }
}

// ---------------------------------------------------------------------------
// Launch
// ---------------------------------------------------------------------------
extern "C" void kernel_launch(void* const* d_in, const int* in_sizes, int n_in,
                              void* d_out, int out_size) {
    const float* x     = (const float*)d_in[0];
    const float* Wqkv  = (const float*)d_in[1];
    const float* bqkv  = (const float*)d_in[2];
    const float* Wproj = (const float*)d_in[3];
    const float* bproj = (const float*)d_in[4];
    float* out = (float*)d_out;

    float *qkv_p, *att_p, *xt_p, *wq_p, *wp_p;
    cudaGetSymbolAddress((void**)&qkv_p, g_qkv);
    cudaGetSymbolAddress((void**)&att_p, g_att);
    cudaGetSymbolAddress((void**)&xt_p,  g_xt);
    cudaGetSymbolAddress((void**)&wq_p,  g_wqkvt);
    cudaGetSymbolAddress((void**)&wp_p,  g_wprojt);

    cudaFuncSetAttribute(gemm_tc<true>,
                         cudaFuncAttributeMaxDynamicSharedMemorySize, GEMM_SMEM);
    cudaFuncSetAttribute(gemm_tc<false>,
                         cudaFuncAttributeMaxDynamicSharedMemorySize, GEMM_SMEM);
    cudaFuncSetAttribute(attn_tc,
                         cudaFuncAttributeMaxDynamicSharedMemorySize, ATTN_SMEM);

    // 0) operand prep: x k-permuted; weights transposed [N][K] + k-permuted
    cvt_x_perm<<<(M_*C_/8)/256, 256>>>((const float4*)x, (float4*)xt_p, M_*C_/8);
    {
        dim3 blk(32, 8);
        dim3 gq(NQKV_/32, C_/32);
        cvt_transpose_perm<<<gq, blk>>>(Wqkv, wq_p, C_, NQKV_);
        dim3 gp(C_/32, C_/32);
        cvt_transpose_perm<<<gp, blk>>>(Wproj, wp_p, C_, C_);
    }

    // 1) QKV GEMM -> d-permuted tf32 qkv
    dim3 g1(NQKV_/128, M_/128);
    gemm_tc<true><<<g1, 128, GEMM_SMEM>>>(xt_p, wq_p, bqkv, qkv_p, M_, NQKV_, C_);

    // 2) Flash attention -> k-permuted tf32 att
    dim3 g2(T_/128, B_*NH_);
    attn_tc<<<g2, 256, ATTN_SMEM>>>(qkv_p, att_p);

    // 3) Output projection -> natural fp32 out
    dim3 g3(C_/128, M_/128);
    gemm_tc<false><<<g3, 128, GEMM_SMEM>>>(att_p, wp_p, bproj, out, M_, C_, C_);
}